// round 7
// baseline (speedup 1.0000x reference)
#include <cuda_runtime.h>
#include <cstdint>

#define NB 64
#define NN 22
#define NF 64
#define NO 64
#define NT 512
#define TT 8              // t-tile width per CTA

typedef unsigned long long u64;

__device__ float d_S[2*NN*NN];   // Chebyshev supports S1, S2 (S0 = I implicit)

// ---------------------------------------------------------------------------
// packed f32x2 helpers (Blackwell)
// ---------------------------------------------------------------------------
__device__ __forceinline__ u64 pk2(float a, float b) {
    u64 r; asm("mov.b64 %0,{%1,%2};" : "=l"(r) : "f"(a), "f"(b)); return r;
}
__device__ __forceinline__ u64 ffma2(u64 a, u64 b, u64 c) {
    u64 d; asm("fma.rn.f32x2 %0,%1,%2,%3;" : "=l"(d) : "l"(a), "l"(b), "l"(c)); return d;
}
__device__ __forceinline__ u64 fmul2(u64 a, u64 b) {
    u64 d; asm("mul.rn.f32x2 %0,%1,%2;" : "=l"(d) : "l"(a), "l"(b)); return d;
}
__device__ __forceinline__ void unpk(u64 v, float& a, float& b) {
    asm("mov.b64 {%0,%1},%2;" : "=f"(a), "=f"(b) : "l"(v));
}

// ---------------------------------------------------------------------------
// K0: supports = softmax(relu(E E^T), axis=1); write S1=supports,
//     S2 = 2*S1@S1 - I.  One block, 512 threads.
// ---------------------------------------------------------------------------
__global__ void k_supports(const float* __restrict__ E) {
    __shared__ float Es[NN*NN];
    __shared__ float P[NN*NN];
    __shared__ float sup[NN*NN];
    int t = threadIdx.x;
    if (t < NN*NN) Es[t] = E[t];
    __syncthreads();
    if (t < NN*NN) {
        int i = t / NN, j = t % NN;
        float s = 0.f;
        #pragma unroll
        for (int l = 0; l < NN; l++) s += Es[i*NN + l] * Es[j*NN + l];
        P[t] = fmaxf(s, 0.f);
    }
    __syncthreads();
    if (t < NN) {
        float mx = -1e30f;
        #pragma unroll
        for (int j = 0; j < NN; j++) mx = fmaxf(mx, P[t*NN + j]);
        float den = 0.f;
        #pragma unroll
        for (int j = 0; j < NN; j++) { float e = expf(P[t*NN + j] - mx); sup[t*NN + j] = e; den += e; }
        float inv = 1.f / den;
        #pragma unroll
        for (int j = 0; j < NN; j++) sup[t*NN + j] *= inv;
    }
    __syncthreads();
    if (t < NN*NN) {
        int i = t / NN, j = t % NN;
        float eye = (i == j) ? 1.f : 0.f;
        d_S[t] = sup[t];                       // S1
        float s = 0.f;
        #pragma unroll
        for (int l = 0; l < NN; l++) s += sup[i*NN + l] * sup[l*NN + j];
        d_S[NN*NN + t] = 2.f * s - eye;        // S2
    }
}

// ---------------------------------------------------------------------------
// Main fused kernel: one CTA per (b, 8-wide t tile). 768 threads, occ 1.
// Phase 1: rhs[k][m][f][t] = sum_n a2*x   (packed f32x2 over t, smem)
// Phase 2: warp=m, lane=o-pair, 8t in regs; rhs loads warp-uniform broadcast.
// ---------------------------------------------------------------------------
__global__ void __launch_bounds__(768, 1) k_main(
    const float* __restrict__ x,
    const float* __restrict__ att,
    const float* __restrict__ theta_g,
    float* __restrict__ out)
{
    extern __shared__ float sm[];
    float* rhs_s   = sm;                                   // [3][22][64][8] = 33792 f
    float* theta_s = sm + 3*NN*NF*TT;                      // [3][64][64]    = 12288 f
    u64*   a2d     = (u64*)(sm + 3*NN*NF*TT + 3*NF*NO);    // [2][22][22] u64
    u64*   diag    = a2d + 2*NN*NN;                        // [22] u64

    const int tid = threadIdx.x;
    const int b   = blockIdx.y;
    const int tt0 = blockIdx.x * TT;

    // ---- stage theta (raw floats) + A2 (duplicated u64 pairs) ----
    {
        const float4* tg = (const float4*)theta_g;
        float4* ts = (float4*)theta_s;
        #pragma unroll
        for (int j = 0; j < 4; j++) ts[tid + j*768] = tg[tid + j*768];
    }
    for (int idx = tid; idx < 2*NN*NN + NN; idx += 768) {
        if (idx < 2*NN*NN) {
            int kk = idx / (NN*NN);
            int r  = idx % (NN*NN);
            int m = r / NN, n = r % NN;
            float v = d_S[kk*NN*NN + n*NN + m] * att[(b*NN + n)*NN + m];
            a2d[idx] = pk2(v, v);
        } else {
            int m = idx - 2*NN*NN;
            float v = att[(b*NN + m)*NN + m];
            diag[m] = pk2(v, v);
        }
    }
    __syncthreads();

    // ---- phase 1: thread = (k, f, t-pair); 3*64*4 = 768 items ----
    const float* xb = x + (size_t)b*NN*NF*NT + tt0;
    {
        const int k  = tid >> 8;           // warp-uniform
        const int f  = (tid >> 2) & 63;
        const int tp = tid & 3;
        float* rw = rhs_s + (size_t)(k*NN)*(NF*TT) + f*TT + tp*2;
        if (k == 0) {
            // S0 = I -> rhs[0][m] = diag[m] * x[m]
            #pragma unroll
            for (int m = 0; m < NN; m++) {
                u64 xv = *(const u64*)(xb + (m*NF + f)*NT + tp*2);
                *(u64*)(rw + m*(NF*TT)) = fmul2(diag[m], xv);
            }
        } else {
            u64 acc[NN];
            #pragma unroll
            for (int m = 0; m < NN; m++) acc[m] = 0ULL;
            const u64* ap = a2d + (k-1)*NN*NN;
            // software-pipelined over n-pairs: prefetch next x while FMA-ing
            u64 xv0 = *(const u64*)(xb + (0*NF + f)*NT + tp*2);
            u64 xv1 = *(const u64*)(xb + (1*NF + f)*NT + tp*2);
            #pragma unroll 1
            for (int c = 0; c < NN/2; c++) {
                u64 c0 = xv0, c1 = xv1;
                if (c < NN/2 - 1) {
                    xv0 = *(const u64*)(xb + ((2*c+2)*NF + f)*NT + tp*2);
                    xv1 = *(const u64*)(xb + ((2*c+3)*NF + f)*NT + tp*2);
                }
                #pragma unroll
                for (int m = 0; m < NN; m++) {
                    ulonglong2 aa = *(const ulonglong2*)(ap + m*NN + 2*c);
                    acc[m] = ffma2(aa.x, c0, acc[m]);
                    acc[m] = ffma2(aa.y, c1, acc[m]);
                }
            }
            #pragma unroll
            for (int m = 0; m < NN; m++)
                *(u64*)(rw + m*(NF*TT)) = acc[m];
        }
    }
    __syncthreads();

    // ---- phase 2: warp = m (22 warps); lane = o-pair; full t=8 in regs ----
    const int w = tid >> 5;
    if (w < NN) {
        const int m    = w;
        const int lane = tid & 31;
        const int o0   = lane * 2;

        u64 acc[2][4];                      // [oo][t-pair]
        #pragma unroll
        for (int j = 0; j < 2; j++)
            #pragma unroll
            for (int p = 0; p < 4; p++) acc[j][p] = 0ULL;

        #pragma unroll
        for (int k = 0; k < 3; k++) {
            const float* th = theta_s + k*NF*NO + o0;
            const float* rr = rhs_s + (size_t)(k*NN + m)*(NF*TT);
            #pragma unroll 8
            for (int f = 0; f < NF; f++) {
                float2 tv = *(const float2*)(th + f*NO);      // 2 distinct o
                u64 t0 = pk2(tv.x, tv.x);
                u64 t1 = pk2(tv.y, tv.y);
                // warp-uniform rhs strip: broadcast, 1 wf per LDS.128
                ulonglong2 ra = *(const ulonglong2*)(rr + f*TT);      // t0..3
                ulonglong2 rb = *(const ulonglong2*)(rr + f*TT + 4);  // t4..7
                acc[0][0] = ffma2(t0, ra.x, acc[0][0]);
                acc[0][1] = ffma2(t0, ra.y, acc[0][1]);
                acc[0][2] = ffma2(t0, rb.x, acc[0][2]);
                acc[0][3] = ffma2(t0, rb.y, acc[0][3]);
                acc[1][0] = ffma2(t1, ra.x, acc[1][0]);
                acc[1][1] = ffma2(t1, ra.y, acc[1][1]);
                acc[1][2] = ffma2(t1, rb.x, acc[1][2]);
                acc[1][3] = ffma2(t1, rb.y, acc[1][3]);
            }
        }

        // epilogue: unpack, relu, 2x float4 store per o
        #pragma unroll
        for (int oo = 0; oo < 2; oo++) {
            float v0, v1, v2, v3, v4, v5, v6, v7;
            unpk(acc[oo][0], v0, v1);
            unpk(acc[oo][1], v2, v3);
            unpk(acc[oo][2], v4, v5);
            unpk(acc[oo][3], v6, v7);
            float* op = out + ((size_t)(b*NN + m)*NO + o0 + oo)*NT + tt0;
            *(float4*)(op)     = make_float4(fmaxf(v0, 0.f), fmaxf(v1, 0.f),
                                             fmaxf(v2, 0.f), fmaxf(v3, 0.f));
            *(float4*)(op + 4) = make_float4(fmaxf(v4, 0.f), fmaxf(v5, 0.f),
                                             fmaxf(v6, 0.f), fmaxf(v7, 0.f));
        }
    }
}

// ---------------------------------------------------------------------------
extern "C" void kernel_launch(void* const* d_in, const int* in_sizes, int n_in,
                              void* d_out, int out_size)
{
    const float* x     = (const float*)d_in[0];   // [B,N,F_in,T]
    const float* att   = (const float*)d_in[1];   // [B,N,N]
    const float* theta = (const float*)d_in[2];   // [K,F_in,F_out]
    const float* emb   = (const float*)d_in[3];   // [N,N]
    float* out = (float*)d_out;                   // [B,N,F_out,T]

    k_supports<<<1, 512>>>(emb);

    size_t smem = (size_t)(3*NN*NF*TT + 3*NF*NO) * sizeof(float)
                + (size_t)(2*NN*NN + NN) * sizeof(u64);
    cudaFuncSetAttribute(k_main, cudaFuncAttributeMaxDynamicSharedMemorySize, (int)smem);
    dim3 grid(NT/TT, NB);
    k_main<<<grid, 768, smem>>>(x, att, theta, out);
}

// round 8
// speedup vs baseline: 1.0019x; 1.0019x over previous
#include <cuda_runtime.h>
#include <cstdint>

#define NB 64
#define NN 22
#define NF 64
#define NO 64
#define NT 512
#define TT 8              // t-tile width per CTA

typedef unsigned long long u64;

__device__ float d_S[2*NN*NN];   // Chebyshev supports S1, S2 (S0 = I implicit)

// ---------------------------------------------------------------------------
// packed f32x2 helpers (Blackwell)
// ---------------------------------------------------------------------------
__device__ __forceinline__ u64 pk2(float a, float b) {
    u64 r; asm("mov.b64 %0,{%1,%2};" : "=l"(r) : "f"(a), "f"(b)); return r;
}
__device__ __forceinline__ u64 ffma2(u64 a, u64 b, u64 c) {
    u64 d; asm("fma.rn.f32x2 %0,%1,%2,%3;" : "=l"(d) : "l"(a), "l"(b), "l"(c)); return d;
}
__device__ __forceinline__ u64 fmul2(u64 a, u64 b) {
    u64 d; asm("mul.rn.f32x2 %0,%1,%2;" : "=l"(d) : "l"(a), "l"(b)); return d;
}
__device__ __forceinline__ void unpk(u64 v, float& a, float& b) {
    asm("mov.b64 {%0,%1},%2;" : "=f"(a), "=f"(b) : "l"(v));
}

// ---------------------------------------------------------------------------
// K0: supports = softmax(relu(E E^T), axis=1); write S1=supports,
//     S2 = 2*S1@S1 - I.  One block, 512 threads.
// ---------------------------------------------------------------------------
__global__ void k_supports(const float* __restrict__ E) {
    __shared__ float Es[NN*NN];
    __shared__ float P[NN*NN];
    __shared__ float sup[NN*NN];
    int t = threadIdx.x;
    if (t < NN*NN) Es[t] = E[t];
    __syncthreads();
    if (t < NN*NN) {
        int i = t / NN, j = t % NN;
        float s = 0.f;
        #pragma unroll
        for (int l = 0; l < NN; l++) s += Es[i*NN + l] * Es[j*NN + l];
        P[t] = fmaxf(s, 0.f);
    }
    __syncthreads();
    if (t < NN) {
        float mx = -1e30f;
        #pragma unroll
        for (int j = 0; j < NN; j++) mx = fmaxf(mx, P[t*NN + j]);
        float den = 0.f;
        #pragma unroll
        for (int j = 0; j < NN; j++) { float e = expf(P[t*NN + j] - mx); sup[t*NN + j] = e; den += e; }
        float inv = 1.f / den;
        #pragma unroll
        for (int j = 0; j < NN; j++) sup[t*NN + j] *= inv;
    }
    __syncthreads();
    if (t < NN*NN) {
        int i = t / NN, j = t % NN;
        float eye = (i == j) ? 1.f : 0.f;
        d_S[t] = sup[t];                       // S1
        float s = 0.f;
        #pragma unroll
        for (int l = 0; l < NN; l++) s += sup[i*NN + l] * sup[l*NN + j];
        d_S[NN*NN + t] = 2.f * s - eye;        // S2
    }
}

// ---------------------------------------------------------------------------
// Main fused kernel: one CTA per (b, 8-wide t tile). 768 threads, occ 1.
// Phase 1: rhs[k][m][f][t] = sum_n a2*x   (packed f32x2 over t, smem)
// Phase 2: warp=m, lane=o-pair, 8t in regs; rhs loads warp-uniform broadcast.
// ---------------------------------------------------------------------------
__global__ void __launch_bounds__(768, 1) k_main(
    const float* __restrict__ x,
    const float* __restrict__ att,
    const float* __restrict__ theta_g,
    float* __restrict__ out)
{
    extern __shared__ float sm[];
    float* rhs_s   = sm;                                   // [3][22][64][8] = 33792 f
    float* theta_s = sm + 3*NN*NF*TT;                      // [3][64][64]    = 12288 f
    u64*   a2d     = (u64*)(sm + 3*NN*NF*TT + 3*NF*NO);    // [2][22][22] u64
    u64*   diag    = a2d + 2*NN*NN;                        // [22] u64

    const int tid = threadIdx.x;
    const int b   = blockIdx.y;
    const int tt0 = blockIdx.x * TT;

    // ---- stage theta (raw floats) + A2 (duplicated u64 pairs) ----
    {
        const float4* tg = (const float4*)theta_g;
        float4* ts = (float4*)theta_s;
        #pragma unroll
        for (int j = 0; j < 4; j++) ts[tid + j*768] = tg[tid + j*768];
    }
    for (int idx = tid; idx < 2*NN*NN + NN; idx += 768) {
        if (idx < 2*NN*NN) {
            int kk = idx / (NN*NN);
            int r  = idx % (NN*NN);
            int m = r / NN, n = r % NN;
            float v = d_S[kk*NN*NN + n*NN + m] * att[(b*NN + n)*NN + m];
            a2d[idx] = pk2(v, v);
        } else {
            int m = idx - 2*NN*NN;
            float v = att[(b*NN + m)*NN + m];
            diag[m] = pk2(v, v);
        }
    }
    __syncthreads();

    // ---- phase 1: thread = (k, f, t-pair); 3*64*4 = 768 items ----
    const float* xb = x + (size_t)b*NN*NF*NT + tt0;
    {
        const int k  = tid >> 8;           // warp-uniform
        const int f  = (tid >> 2) & 63;
        const int tp = tid & 3;
        float* rw = rhs_s + (size_t)(k*NN)*(NF*TT) + f*TT + tp*2;
        if (k == 0) {
            // S0 = I -> rhs[0][m] = diag[m] * x[m]
            #pragma unroll
            for (int m = 0; m < NN; m++) {
                u64 xv = *(const u64*)(xb + (m*NF + f)*NT + tp*2);
                *(u64*)(rw + m*(NF*TT)) = fmul2(diag[m], xv);
            }
        } else {
            u64 acc[NN];
            #pragma unroll
            for (int m = 0; m < NN; m++) acc[m] = 0ULL;
            const u64* ap = a2d + (k-1)*NN*NN;
            // software-pipelined over n-pairs: prefetch next x while FMA-ing
            u64 xv0 = *(const u64*)(xb + (0*NF + f)*NT + tp*2);
            u64 xv1 = *(const u64*)(xb + (1*NF + f)*NT + tp*2);
            #pragma unroll 1
            for (int c = 0; c < NN/2; c++) {
                u64 c0 = xv0, c1 = xv1;
                if (c < NN/2 - 1) {
                    xv0 = *(const u64*)(xb + ((2*c+2)*NF + f)*NT + tp*2);
                    xv1 = *(const u64*)(xb + ((2*c+3)*NF + f)*NT + tp*2);
                }
                #pragma unroll
                for (int m = 0; m < NN; m++) {
                    ulonglong2 aa = *(const ulonglong2*)(ap + m*NN + 2*c);
                    acc[m] = ffma2(aa.x, c0, acc[m]);
                    acc[m] = ffma2(aa.y, c1, acc[m]);
                }
            }
            #pragma unroll
            for (int m = 0; m < NN; m++)
                *(u64*)(rw + m*(NF*TT)) = acc[m];
        }
    }
    __syncthreads();

    // ---- phase 2: warp = m (22 warps); lane = o-pair; full t=8 in regs ----
    const int w = tid >> 5;
    if (w < NN) {
        const int m    = w;
        const int lane = tid & 31;
        const int o0   = lane * 2;

        u64 acc[2][4];                      // [oo][t-pair]
        #pragma unroll
        for (int j = 0; j < 2; j++)
            #pragma unroll
            for (int p = 0; p < 4; p++) acc[j][p] = 0ULL;

        #pragma unroll
        for (int k = 0; k < 3; k++) {
            const float* th = theta_s + k*NF*NO + o0;
            const float* rr = rhs_s + (size_t)(k*NN + m)*(NF*TT);
            #pragma unroll 8
            for (int f = 0; f < NF; f++) {
                float2 tv = *(const float2*)(th + f*NO);      // 2 distinct o
                u64 t0 = pk2(tv.x, tv.x);
                u64 t1 = pk2(tv.y, tv.y);
                // warp-uniform rhs strip: broadcast, 1 wf per LDS.128
                ulonglong2 ra = *(const ulonglong2*)(rr + f*TT);      // t0..3
                ulonglong2 rb = *(const ulonglong2*)(rr + f*TT + 4);  // t4..7
                acc[0][0] = ffma2(t0, ra.x, acc[0][0]);
                acc[0][1] = ffma2(t0, ra.y, acc[0][1]);
                acc[0][2] = ffma2(t0, rb.x, acc[0][2]);
                acc[0][3] = ffma2(t0, rb.y, acc[0][3]);
                acc[1][0] = ffma2(t1, ra.x, acc[1][0]);
                acc[1][1] = ffma2(t1, ra.y, acc[1][1]);
                acc[1][2] = ffma2(t1, rb.x, acc[1][2]);
                acc[1][3] = ffma2(t1, rb.y, acc[1][3]);
            }
        }

        // epilogue: unpack, relu, 2x float4 store per o
        #pragma unroll
        for (int oo = 0; oo < 2; oo++) {
            float v0, v1, v2, v3, v4, v5, v6, v7;
            unpk(acc[oo][0], v0, v1);
            unpk(acc[oo][1], v2, v3);
            unpk(acc[oo][2], v4, v5);
            unpk(acc[oo][3], v6, v7);
            float* op = out + ((size_t)(b*NN + m)*NO + o0 + oo)*NT + tt0;
            *(float4*)(op)     = make_float4(fmaxf(v0, 0.f), fmaxf(v1, 0.f),
                                             fmaxf(v2, 0.f), fmaxf(v3, 0.f));
            *(float4*)(op + 4) = make_float4(fmaxf(v4, 0.f), fmaxf(v5, 0.f),
                                             fmaxf(v6, 0.f), fmaxf(v7, 0.f));
        }
    }
}

// ---------------------------------------------------------------------------
extern "C" void kernel_launch(void* const* d_in, const int* in_sizes, int n_in,
                              void* d_out, int out_size)
{
    const float* x     = (const float*)d_in[0];   // [B,N,F_in,T]
    const float* att   = (const float*)d_in[1];   // [B,N,N]
    const float* theta = (const float*)d_in[2];   // [K,F_in,F_out]
    const float* emb   = (const float*)d_in[3];   // [N,N]
    float* out = (float*)d_out;                   // [B,N,F_out,T]

    k_supports<<<1, 512>>>(emb);

    size_t smem = (size_t)(3*NN*NF*TT + 3*NF*NO) * sizeof(float)
                + (size_t)(2*NN*NN + NN) * sizeof(u64);
    cudaFuncSetAttribute(k_main, cudaFuncAttributeMaxDynamicSharedMemorySize, (int)smem);
    dim3 grid(NT/TT, NB);
    k_main<<<grid, 768, smem>>>(x, att, theta, out);
}

// round 10
// speedup vs baseline: 1.3901x; 1.3874x over previous
#include <cuda_runtime.h>
#include <cuda_bf16.h>
#include <cstdint>

#define NB 64
#define NN 22
#define NF 64
#define NO 64
#define NT 512
#define TT 8              // t-tile width per CTA
#define KF 192            // combined (k,f) contraction dim
#define MT 176            // combined (m,t) rows = 22*8

typedef unsigned long long u64;

__device__ float d_S[2*NN*NN];   // Chebyshev supports S1, S2 (S0 = I implicit)

// ---------------------------------------------------------------------------
// packed f32x2 helpers
// ---------------------------------------------------------------------------
__device__ __forceinline__ u64 pk2(float a, float b) {
    u64 r; asm("mov.b64 %0,{%1,%2};" : "=l"(r) : "f"(a), "f"(b)); return r;
}
__device__ __forceinline__ u64 ffma2(u64 a, u64 b, u64 c) {
    u64 d; asm("fma.rn.f32x2 %0,%1,%2,%3;" : "=l"(d) : "l"(a), "l"(b), "l"(c)); return d;
}
__device__ __forceinline__ u64 fmul2(u64 a, u64 b) {
    u64 d; asm("mul.rn.f32x2 %0,%1,%2;" : "=l"(d) : "l"(a), "l"(b)); return d;
}
__device__ __forceinline__ void unpk(u64 v, float& a, float& b) {
    asm("mov.b64 {%0,%1},%2;" : "=f"(a), "=f"(b) : "l"(v));
}
__device__ __forceinline__ uint32_t smem_u32(const void* p) {
    uint32_t a;
    asm("{ .reg .u64 t; cvta.to.shared.u64 t, %1; cvt.u32.u64 %0, t; }"
        : "=r"(a) : "l"(p));
    return a;
}

// ---------------------------------------------------------------------------
// warp-mma building blocks (sm_80+ features only; no 'a'-target needed)
// ---------------------------------------------------------------------------
#define LDSM4T(R, ADDR) \
    asm volatile("ldmatrix.sync.aligned.m8n8.x4.trans.shared.b16 {%0,%1,%2,%3}, [%4];" \
        : "=r"((R)[0]), "=r"((R)[1]), "=r"((R)[2]), "=r"((R)[3]) : "r"(ADDR))

#define MMA16816(D, A, B0, B1) \
    asm volatile("mma.sync.aligned.m16n8k16.row.col.f32.bf16.bf16.f32 " \
        "{%0,%1,%2,%3}, {%4,%5,%6,%7}, {%8,%9}, {%0,%1,%2,%3};" \
        : "+f"((D)[0]), "+f"((D)[1]), "+f"((D)[2]), "+f"((D)[3]) \
        : "r"((A)[0]), "r"((A)[1]), "r"((A)[2]), "r"((A)[3]), "r"(B0), "r"(B1))

// SMEM geometry (bytes)
#define A_STRIDE 368      // 92 u32 per kf-row (176 bf16 used; conflict-free)
#define B_STRIDE 144      // 72 bf16 per kf-row (64 used; conflict-free)
#define A_BYTES  (KF*A_STRIDE)         // 70656
#define OFF_ALO  A_BYTES               // 70656
#define OFF_BHI  (2*A_BYTES)           // 141312
#define OFF_BLO  (2*A_BYTES + KF*B_STRIDE)   // 168960
#define DSMEM_TOTAL (2*A_BYTES + 2*KF*B_STRIDE)  // 196608

// ---------------------------------------------------------------------------
// K0: supports = softmax(relu(E E^T), axis=1); S1, S2 = 2*S1@S1 - I
// ---------------------------------------------------------------------------
__global__ void k_supports(const float* __restrict__ E) {
    __shared__ float Es[NN*NN];
    __shared__ float P[NN*NN];
    __shared__ float sup[NN*NN];
    int t = threadIdx.x;
    if (t < NN*NN) Es[t] = E[t];
    __syncthreads();
    if (t < NN*NN) {
        int i = t / NN, j = t % NN;
        float s = 0.f;
        #pragma unroll
        for (int l = 0; l < NN; l++) s += Es[i*NN + l] * Es[j*NN + l];
        P[t] = fmaxf(s, 0.f);
    }
    __syncthreads();
    if (t < NN) {
        float mx = -1e30f;
        #pragma unroll
        for (int j = 0; j < NN; j++) mx = fmaxf(mx, P[t*NN + j]);
        float den = 0.f;
        #pragma unroll
        for (int j = 0; j < NN; j++) { float e = expf(P[t*NN + j] - mx); sup[t*NN + j] = e; den += e; }
        float inv = 1.f / den;
        #pragma unroll
        for (int j = 0; j < NN; j++) sup[t*NN + j] *= inv;
    }
    __syncthreads();
    if (t < NN*NN) {
        int i = t / NN, j = t % NN;
        float eye = (i == j) ? 1.f : 0.f;
        d_S[t] = sup[t];                       // S1
        float s = 0.f;
        #pragma unroll
        for (int l = 0; l < NN; l++) s += sup[i*NN + l] * sup[l*NN + j];
        d_S[NN*NN + t] = 2.f * s - eye;        // S2
    }
}

// ---------------------------------------------------------------------------
// Fused main kernel. One CTA per (b, 8-wide t-tile). 768 threads, occ 1.
// Phase 1: n-contraction (packed FFMA2, R6-proven), split to bf16 hi/lo,
//          store to A[kf][mt] (K-major) in SMEM.
// Phase 2: warp-mma bf16 3-term (hh+hl+lh) D[mt,o]; relu; store.
// ---------------------------------------------------------------------------
__global__ void __launch_bounds__(768, 1) k_main(
    const float* __restrict__ x,
    const float* __restrict__ att,
    const float* __restrict__ theta_g,
    float* __restrict__ out)
{
    extern __shared__ char dsm[];
    uint32_t* A_hi32 = (uint32_t*)dsm;                    // [KF][92] u32
    uint32_t* A_lo32 = (uint32_t*)(dsm + OFF_ALO);
    __shared__ u64 a2d[2*NN*NN];
    __shared__ u64 diag[NN];

    const int tid = threadIdx.x;
    const int b   = blockIdx.y;
    const int tt0 = blockIdx.x * TT;
    const uint32_t sbase = smem_u32(dsm);

    // ---- stage theta hi/lo into B[kf][o] (bf16, stride 144B) ----
    for (int i = tid; i < KF*NO/2; i += 768) {            // 6144 items, o-pairs
        int kf = i >> 5;
        int op = (i & 31) * 2;
        float2 v = *(const float2*)(theta_g + kf*NO + op);
        __nv_bfloat162 h = __floats2bfloat162_rn(v.x, v.y);
        float hx = __bfloat162float(__low2bfloat16(h));
        float hy = __bfloat162float(__high2bfloat16(h));
        __nv_bfloat162 l = __floats2bfloat162_rn(v.x - hx, v.y - hy);
        *(uint32_t*)(dsm + OFF_BHI + kf*B_STRIDE + op*2) = *(uint32_t*)&h;
        *(uint32_t*)(dsm + OFF_BLO + kf*B_STRIDE + op*2) = *(uint32_t*)&l;
    }
    // ---- stage a2d (dup u64) + diag ----
    for (int idx = tid; idx < 2*NN*NN + NN; idx += 768) {
        if (idx < 2*NN*NN) {
            int kk = idx / (NN*NN);
            int r  = idx % (NN*NN);
            int m = r / NN, n = r % NN;
            float v = d_S[kk*NN*NN + n*NN + m] * att[(b*NN + n)*NN + m];
            a2d[idx] = pk2(v, v);
        } else {
            int m = idx - 2*NN*NN;
            diag[m] = pk2(att[(b*NN + m)*NN + m], att[(b*NN + m)*NN + m]);
        }
    }
    __syncthreads();

    // ---- phase 1: thread = (k, f, t-pair); 3*64*4 = 768 items ----
    {
        const float* xb = x + (size_t)b*NN*NF*NT + tt0;
        const int k  = tid >> 8;            // warp-uniform
        const int f  = (tid >> 2) & 63;
        const int tp = tid & 3;

        u64 acc[NN];
        if (k == 0) {
            #pragma unroll
            for (int m = 0; m < NN; m++) {
                u64 xv = *(const u64*)(xb + (m*NF + f)*NT + tp*2);
                acc[m] = fmul2(diag[m], xv);
            }
        } else {
            #pragma unroll
            for (int m = 0; m < NN; m++) acc[m] = 0ULL;
            const u64* ap = a2d + (k-1)*NN*NN;
            #pragma unroll 1
            for (int c = 0; c < NN/2; c++) {
                u64 xv0 = *(const u64*)(xb + ((2*c+0)*NF + f)*NT + tp*2);
                u64 xv1 = *(const u64*)(xb + ((2*c+1)*NF + f)*NT + tp*2);
                #pragma unroll
                for (int m = 0; m < NN; m++) {
                    ulonglong2 aa = *(const ulonglong2*)(ap + m*NN + 2*c);
                    acc[m] = ffma2(aa.x, xv0, acc[m]);
                    acc[m] = ffma2(aa.y, xv1, acc[m]);
                }
            }
        }
        // split to bf16 hi/lo; A[kf][mt]: row = k*64+f, u32 col = m*4+tp
        uint32_t* rhi = A_hi32 + (k*64 + f)*(A_STRIDE/4) + tp;
        uint32_t* rlo = A_lo32 + (k*64 + f)*(A_STRIDE/4) + tp;
        #pragma unroll
        for (int m = 0; m < NN; m++) {
            float v0, v1; unpk(acc[m], v0, v1);
            __nv_bfloat162 h = __floats2bfloat162_rn(v0, v1);
            float h0 = __bfloat162float(__low2bfloat16(h));
            float h1 = __bfloat162float(__high2bfloat16(h));
            __nv_bfloat162 l = __floats2bfloat162_rn(v0 - h0, v1 - h1);
            rhi[m*4] = *(uint32_t*)&h;
            rlo[m*4] = *(uint32_t*)&l;
        }
    }
    __syncthreads();

    // ---- phase 2: warp = (m16-tile of 11, n32-half); mma.sync bf16 3-term ----
    const int w = tid >> 5;
    if (w < 22) {
        const int lane = tid & 31;
        const int mt  = w >> 1;             // 0..10
        const int nh  = w & 1;              // 0..1
        const int m0b = mt * 16;            // A bf16-col base (mt rows)
        const int n0  = nh * 32;

        // ldmatrix.x4.trans lane address components
        const int lrow  = (lane & 7) + ((lane >> 4) << 3);   // kf-row offset in k16
        const int lga   = ((lane >> 3) & 1) * 8;             // 8-col group select
        uint32_t aA = sbase + lrow*A_STRIDE + (m0b + lga)*2;
        uint32_t aB0 = sbase + OFF_BHI + lrow*B_STRIDE + (n0 + lga)*2;
        uint32_t aB1 = aB0 + 32;                             // n0+16 block

        float acc[16];
        #pragma unroll
        for (int i = 0; i < 16; i++) acc[i] = 0.f;

        #pragma unroll 2
        for (int s = 0; s < 12; s++) {
            uint32_t ah[4], al[4], bh0[4], bh1[4], bl0[4], bl1[4];
            uint32_t ka = aA + s*(16*A_STRIDE);
            uint32_t kb0 = aB0 + s*(16*B_STRIDE);
            uint32_t kb1 = aB1 + s*(16*B_STRIDE);
            LDSM4T(ah, ka);
            LDSM4T(al, ka + (uint32_t)OFF_ALO);
            LDSM4T(bh0, kb0);
            LDSM4T(bh1, kb1);
            LDSM4T(bl0, kb0 + (uint32_t)(OFF_BLO - OFF_BHI));
            LDSM4T(bl1, kb1 + (uint32_t)(OFF_BLO - OFF_BHI));
            // n8 block j: B frag {x4[j&1 ? 1 : 0], x4[.. +2]} from bh0/bh1
            MMA16816(acc +  0, ah, bh0[0], bh0[2]);
            MMA16816(acc +  0, ah, bl0[0], bl0[2]);
            MMA16816(acc +  0, al, bh0[0], bh0[2]);
            MMA16816(acc +  4, ah, bh0[1], bh0[3]);
            MMA16816(acc +  4, ah, bl0[1], bl0[3]);
            MMA16816(acc +  4, al, bh0[1], bh0[3]);
            MMA16816(acc +  8, ah, bh1[0], bh1[2]);
            MMA16816(acc +  8, ah, bl1[0], bl1[2]);
            MMA16816(acc +  8, al, bh1[0], bh1[2]);
            MMA16816(acc + 12, ah, bh1[1], bh1[3]);
            MMA16816(acc + 12, ah, bl1[1], bl1[3]);
            MMA16816(acc + 12, al, bh1[1], bh1[3]);
        }

        // ---- epilogue: D(row=mt-row, col=o) -> relu -> out[b][m][o][t] ----
        // frag: c0,c1 row=lane/4, cols q*2,q*2+1; c2,c3 row=lane/4+8
        const int tloc = lane >> 2;         // t offset within tile
        const int q2   = (lane & 3) * 2;
        #pragma unroll
        for (int j = 0; j < 4; j++) {
            #pragma unroll
            for (int i = 0; i < 2; i++) {
                int m = mt*2 + i;           // (m0b + lane/4 + 8i)/8
                int o = n0 + j*8 + q2;
                float* op = out + ((size_t)(b*NN + m)*NO + o)*NT + tt0 + tloc;
                op[0]  = fmaxf(acc[j*4 + i*2 + 0], 0.f);
                op[NT] = fmaxf(acc[j*4 + i*2 + 1], 0.f);
            }
        }
    }
}

// ---------------------------------------------------------------------------
extern "C" void kernel_launch(void* const* d_in, const int* in_sizes, int n_in,
                              void* d_out, int out_size)
{
    const float* x     = (const float*)d_in[0];   // [B,N,F_in,T]
    const float* att   = (const float*)d_in[1];   // [B,N,N]
    const float* theta = (const float*)d_in[2];   // [K,F_in,F_out]
    const float* emb   = (const float*)d_in[3];   // [N,N]
    float* out = (float*)d_out;                   // [B,N,F_out,T]

    k_supports<<<1, 512>>>(emb);

    cudaFuncSetAttribute(k_main, cudaFuncAttributeMaxDynamicSharedMemorySize,
                         DSMEM_TOTAL);
    dim3 grid(NT/TT, NB);
    k_main<<<grid, 768, DSMEM_TOTAL>>>(x, att, theta, out);
}

// round 11
// speedup vs baseline: 1.4197x; 1.0213x over previous
#include <cuda_runtime.h>
#include <cuda_bf16.h>
#include <cstdint>

#define NB 64
#define NN 22
#define NF 64
#define NO 64
#define NT 512
#define TT 8              // t-tile width per CTA
#define KF 192            // combined (k,f) contraction dim
#define MT 176            // combined (m,t) rows = 22*8

typedef unsigned long long u64;

__device__ float d_S[2*NN*NN];   // Chebyshev supports S1, S2 (S0 = I implicit)

// ---------------------------------------------------------------------------
// packed f32x2 helpers
// ---------------------------------------------------------------------------
__device__ __forceinline__ u64 pk2(float a, float b) {
    u64 r; asm("mov.b64 %0,{%1,%2};" : "=l"(r) : "f"(a), "f"(b)); return r;
}
__device__ __forceinline__ u64 ffma2(u64 a, u64 b, u64 c) {
    u64 d; asm("fma.rn.f32x2 %0,%1,%2,%3;" : "=l"(d) : "l"(a), "l"(b), "l"(c)); return d;
}
__device__ __forceinline__ u64 fmul2(u64 a, u64 b) {
    u64 d; asm("mul.rn.f32x2 %0,%1,%2;" : "=l"(d) : "l"(a), "l"(b)); return d;
}
__device__ __forceinline__ void unpk(u64 v, float& a, float& b) {
    asm("mov.b64 {%0,%1},%2;" : "=f"(a), "=f"(b) : "l"(v));
}
__device__ __forceinline__ uint32_t smem_u32(const void* p) {
    uint32_t a;
    asm("{ .reg .u64 t; cvta.to.shared.u64 t, %1; cvt.u32.u64 %0, t; }"
        : "=r"(a) : "l"(p));
    return a;
}
__device__ __forceinline__ void cp_async16(uint32_t dst, const void* src) {
    asm volatile("cp.async.ca.shared.global [%0], [%1], 16;"
                 :: "r"(dst), "l"(src) : "memory");
}
#define CP_COMMIT() asm volatile("cp.async.commit_group;" ::: "memory")
#define CP_WAIT2()  asm volatile("cp.async.wait_group 2;" ::: "memory")

// ---------------------------------------------------------------------------
// warp-mma building blocks (sm_80+ features only; no 'a'-target needed)
// ---------------------------------------------------------------------------
#define LDSM4T(R, ADDR) \
    asm volatile("ldmatrix.sync.aligned.m8n8.x4.trans.shared.b16 {%0,%1,%2,%3}, [%4];" \
        : "=r"((R)[0]), "=r"((R)[1]), "=r"((R)[2]), "=r"((R)[3]) : "r"(ADDR))

#define MMA16816(D, A, B0, B1) \
    asm volatile("mma.sync.aligned.m16n8k16.row.col.f32.bf16.bf16.f32 " \
        "{%0,%1,%2,%3}, {%4,%5,%6,%7}, {%8,%9}, {%0,%1,%2,%3};" \
        : "+f"((D)[0]), "+f"((D)[1]), "+f"((D)[2]), "+f"((D)[3]) \
        : "r"((A)[0]), "r"((A)[1]), "r"((A)[2]), "r"((A)[3]), "r"(B0), "r"(B1))

// SMEM geometry (bytes)
#define A_STRIDE 368      // 92 u32 per kf-row (176 bf16 used; conflict-free)
#define B_STRIDE 144      // 72 bf16 per kf-row (64 used; conflict-free)
#define A_BYTES  (KF*A_STRIDE)               // 70656
#define OFF_ALO  A_BYTES                     // 70656
#define OFF_BHI  (2*A_BYTES)                 // 141312
#define OFF_BLO  (2*A_BYTES + KF*B_STRIDE)   // 168960
#define XS_OFF   (2*A_BYTES + 2*KF*B_STRIDE) // 196608: x ring, 4 slots x 4096 B
#define DSMEM_TOTAL (XS_OFF + 4*4096)        // 212992

// ---------------------------------------------------------------------------
// K0: supports = softmax(relu(E E^T), axis=1); S1, S2 = 2*S1@S1 - I
// ---------------------------------------------------------------------------
__global__ void k_supports(const float* __restrict__ E) {
    __shared__ float Es[NN*NN];
    __shared__ float P[NN*NN];
    __shared__ float sup[NN*NN];
    int t = threadIdx.x;
    if (t < NN*NN) Es[t] = E[t];
    __syncthreads();
    if (t < NN*NN) {
        int i = t / NN, j = t % NN;
        float s = 0.f;
        #pragma unroll
        for (int l = 0; l < NN; l++) s += Es[i*NN + l] * Es[j*NN + l];
        P[t] = fmaxf(s, 0.f);
    }
    __syncthreads();
    if (t < NN) {
        float mx = -1e30f;
        #pragma unroll
        for (int j = 0; j < NN; j++) mx = fmaxf(mx, P[t*NN + j]);
        float den = 0.f;
        #pragma unroll
        for (int j = 0; j < NN; j++) { float e = expf(P[t*NN + j] - mx); sup[t*NN + j] = e; den += e; }
        float inv = 1.f / den;
        #pragma unroll
        for (int j = 0; j < NN; j++) sup[t*NN + j] *= inv;
    }
    __syncthreads();
    if (t < NN*NN) {
        int i = t / NN, j = t % NN;
        float eye = (i == j) ? 1.f : 0.f;
        d_S[t] = sup[t];                       // S1
        float s = 0.f;
        #pragma unroll
        for (int l = 0; l < NN; l++) s += sup[i*NN + l] * sup[l*NN + j];
        d_S[NN*NN + t] = 2.f * s - eye;        // S2
    }
}

// ---------------------------------------------------------------------------
// Fused main kernel. One CTA per (b, 8-wide t-tile). 768 threads, occ 1.
// Phase 1: n-contraction via cp.async-pipelined x chunks (depth-4 SMEM ring),
//          packed FFMA2, split to bf16 hi/lo, store A[kf][mt] K-major.
// Phase 2: warp-mma bf16 3-term (hh+hl+lh) D[mt,o]; relu; store. (R10-proven)
// ---------------------------------------------------------------------------
__global__ void __launch_bounds__(768, 1) k_main(
    const float* __restrict__ x,
    const float* __restrict__ att,
    const float* __restrict__ theta_g,
    float* __restrict__ out)
{
    extern __shared__ char dsm[];
    uint32_t* A_hi32 = (uint32_t*)dsm;                    // [KF][92] u32
    uint32_t* A_lo32 = (uint32_t*)(dsm + OFF_ALO);
    __shared__ u64 a2d[2*NN*NN];
    __shared__ u64 diag[NN];

    const int tid = threadIdx.x;
    const int b   = blockIdx.y;
    const int tt0 = blockIdx.x * TT;
    const uint32_t sbase = smem_u32(dsm);
    const uint32_t xsb   = sbase + XS_OFF;
    const float*   xb    = x + (size_t)b*NN*NF*NT + tt0;
    const float*   xsf   = (const float*)(dsm + XS_OFF);

    // cp.async chunk issue: chunk c = n rows {2c, 2c+1}, 4 KB, 256 issuers
    const int cn2 = tid >> 7;          // 0..1   (valid for tid<256)
    const int cf  = (tid >> 1) & 63;
    const int chf = tid & 1;
    const float*  csrc0 = xb + ((size_t)cn2*NF + cf)*NT + chf*4;
    const uint32_t cdst0 = xsb + (uint32_t)((cn2 << 11) | (cf << 5) | (chf << 4));

    // ---- prologue: prefetch chunks 0..2 (overlaps with staging below) ----
    if (tid < 256) {
        cp_async16(cdst0,          csrc0);                 CP_COMMIT();
        cp_async16(cdst0 + 4096,   csrc0 + 2*NF*NT);       CP_COMMIT();
        cp_async16(cdst0 + 8192,   csrc0 + 4*NF*NT);       CP_COMMIT();
    }

    // ---- stage theta hi/lo into B[kf][o] (bf16, stride 144B) ----
    for (int i = tid; i < KF*NO/2; i += 768) {            // 6144 items, o-pairs
        int kf = i >> 5;
        int op = (i & 31) * 2;
        float2 v = *(const float2*)(theta_g + kf*NO + op);
        __nv_bfloat162 h = __floats2bfloat162_rn(v.x, v.y);
        float hx = __bfloat162float(__low2bfloat16(h));
        float hy = __bfloat162float(__high2bfloat16(h));
        __nv_bfloat162 l = __floats2bfloat162_rn(v.x - hx, v.y - hy);
        *(uint32_t*)(dsm + OFF_BHI + kf*B_STRIDE + op*2) = *(uint32_t*)&h;
        *(uint32_t*)(dsm + OFF_BLO + kf*B_STRIDE + op*2) = *(uint32_t*)&l;
    }
    // ---- stage a2d (dup u64) + diag ----
    for (int idx = tid; idx < 2*NN*NN + NN; idx += 768) {
        if (idx < 2*NN*NN) {
            int kk = idx / (NN*NN);
            int r  = idx % (NN*NN);
            int m = r / NN, n = r % NN;
            float v = d_S[kk*NN*NN + n*NN + m] * att[(b*NN + n)*NN + m];
            a2d[idx] = pk2(v, v);
        } else {
            int m = idx - 2*NN*NN;
            diag[m] = pk2(att[(b*NN + m)*NN + m], att[(b*NN + m)*NN + m]);
        }
    }
    __syncthreads();

    // ---- phase 1: thread = (k, f, t-pair); pipelined over n-pair chunks ----
    {
        const int k  = tid >> 8;            // warp-uniform
        const int f  = (tid >> 2) & 63;
        const int tp = tid & 3;
        const u64* ap = a2d + (k >= 1 ? (k-1)*NN*NN : 0);

        u64 acc[NN];
        #pragma unroll
        for (int m = 0; m < NN; m++) acc[m] = 0ULL;

        #pragma unroll
        for (int c = 0; c < NN/2; c++) {
            // chunk c ready? (commits so far = 3 + c; wait<=2 => chunk c done)
            if (tid < 256) CP_WAIT2();
            __syncthreads();
            // prefetch chunk c+3 into ring slot (c+3)&3 (readers of that slot
            // finished compute(c-1) before the barrier above)
            if (tid < 256) {
                if (c + 3 < NN/2)
                    cp_async16(cdst0 + (((c+3) & 3) << 12),
                               csrc0 + (size_t)(2*(c+3))*NF*NT);
                CP_COMMIT();
            }
            // consume slot c&3
            const float* xp = xsf + ((c & 3) << 10);
            u64 xv0 = *(const u64*)(xp + f*8 + tp*2);
            u64 xv1 = *(const u64*)(xp + 512 + f*8 + tp*2);
            if (k == 0) {
                acc[2*c]   = fmul2(diag[2*c],   xv0);
                acc[2*c+1] = fmul2(diag[2*c+1], xv1);
            } else {
                #pragma unroll
                for (int m = 0; m < NN; m++) {
                    ulonglong2 aa = *(const ulonglong2*)(ap + m*NN + 2*c);
                    acc[m] = ffma2(aa.x, xv0, acc[m]);
                    acc[m] = ffma2(aa.y, xv1, acc[m]);
                }
            }
        }

        // split to bf16 hi/lo; A[kf][mt]: row = k*64+f, u32 col = m*4+tp
        uint32_t* rhi = A_hi32 + (k*64 + f)*(A_STRIDE/4) + tp;
        uint32_t* rlo = A_lo32 + (k*64 + f)*(A_STRIDE/4) + tp;
        #pragma unroll
        for (int m = 0; m < NN; m++) {
            float v0, v1; unpk(acc[m], v0, v1);
            __nv_bfloat162 h = __floats2bfloat162_rn(v0, v1);
            float h0 = __bfloat162float(__low2bfloat16(h));
            float h1 = __bfloat162float(__high2bfloat16(h));
            __nv_bfloat162 l = __floats2bfloat162_rn(v0 - h0, v1 - h1);
            rhi[m*4] = *(uint32_t*)&h;
            rlo[m*4] = *(uint32_t*)&l;
        }
    }
    __syncthreads();

    // ---- phase 2: warp = (m16-tile of 11, n32-half); mma.sync bf16 3-term ----
    const int w = tid >> 5;
    if (w < 22) {
        const int lane = tid & 31;
        const int mt  = w >> 1;             // 0..10
        const int nh  = w & 1;              // 0..1
        const int m0b = mt * 16;            // A bf16-col base (mt rows)
        const int n0  = nh * 32;

        // ldmatrix.x4.trans lane address components
        const int lrow  = (lane & 7) + ((lane >> 4) << 3);   // kf-row offset in k16
        const int lga   = ((lane >> 3) & 1) * 8;             // 8-col group select
        uint32_t aA = sbase + lrow*A_STRIDE + (m0b + lga)*2;
        uint32_t aB0 = sbase + OFF_BHI + lrow*B_STRIDE + (n0 + lga)*2;
        uint32_t aB1 = aB0 + 32;                             // n0+16 block

        float acc[16];
        #pragma unroll
        for (int i = 0; i < 16; i++) acc[i] = 0.f;

        #pragma unroll 2
        for (int s = 0; s < 12; s++) {
            uint32_t ah[4], al[4], bh0[4], bh1[4], bl0[4], bl1[4];
            uint32_t ka = aA + s*(16*A_STRIDE);
            uint32_t kb0 = aB0 + s*(16*B_STRIDE);
            uint32_t kb1 = aB1 + s*(16*B_STRIDE);
            LDSM4T(ah, ka);
            LDSM4T(al, ka + (uint32_t)OFF_ALO);
            LDSM4T(bh0, kb0);
            LDSM4T(bh1, kb1);
            LDSM4T(bl0, kb0 + (uint32_t)(OFF_BLO - OFF_BHI));
            LDSM4T(bl1, kb1 + (uint32_t)(OFF_BLO - OFF_BHI));
            MMA16816(acc +  0, ah, bh0[0], bh0[2]);
            MMA16816(acc +  0, ah, bl0[0], bl0[2]);
            MMA16816(acc +  0, al, bh0[0], bh0[2]);
            MMA16816(acc +  4, ah, bh0[1], bh0[3]);
            MMA16816(acc +  4, ah, bl0[1], bl0[3]);
            MMA16816(acc +  4, al, bh0[1], bh0[3]);
            MMA16816(acc +  8, ah, bh1[0], bh1[2]);
            MMA16816(acc +  8, ah, bl1[0], bl1[2]);
            MMA16816(acc +  8, al, bh1[0], bh1[2]);
            MMA16816(acc + 12, ah, bh1[1], bh1[3]);
            MMA16816(acc + 12, ah, bl1[1], bl1[3]);
            MMA16816(acc + 12, al, bh1[1], bh1[3]);
        }

        // ---- epilogue: D(row=mt-row, col=o) -> relu -> out[b][m][o][t] ----
        const int tloc = lane >> 2;         // t offset within tile
        const int q2   = (lane & 3) * 2;
        #pragma unroll
        for (int j = 0; j < 4; j++) {
            #pragma unroll
            for (int i = 0; i < 2; i++) {
                int m = mt*2 + i;
                int o = n0 + j*8 + q2;
                float* op = out + ((size_t)(b*NN + m)*NO + o)*NT + tt0 + tloc;
                op[0]  = fmaxf(acc[j*4 + i*2 + 0], 0.f);
                op[NT] = fmaxf(acc[j*4 + i*2 + 1], 0.f);
            }
        }
    }
}

// ---------------------------------------------------------------------------
extern "C" void kernel_launch(void* const* d_in, const int* in_sizes, int n_in,
                              void* d_out, int out_size)
{
    const float* x     = (const float*)d_in[0];   // [B,N,F_in,T]
    const float* att   = (const float*)d_in[1];   // [B,N,N]
    const float* theta = (const float*)d_in[2];   // [K,F_in,F_out]
    const float* emb   = (const float*)d_in[3];   // [N,N]
    float* out = (float*)d_out;                   // [B,N,F_out,T]

    k_supports<<<1, 512>>>(emb);

    cudaFuncSetAttribute(k_main, cudaFuncAttributeMaxDynamicSharedMemorySize,
                         DSMEM_TOTAL);
    dim3 grid(NT/TT, NB);
    k_main<<<grid, 768, DSMEM_TOTAL>>>(x, att, theta, out);
}

// round 12
// speedup vs baseline: 1.5263x; 1.0751x over previous
#include <cuda_runtime.h>
#include <cuda_fp16.h>
#include <cstdint>

#define NB 64
#define NN 22
#define NF 64
#define NO 64
#define NT 512
#define TT 4              // t-tile width per CTA
#define KF 192            // combined (k,f) contraction dim
#define MTP 96            // padded (m,t) rows: 22*4 = 88 -> 96 (6 m16 tiles)

typedef unsigned long long u64;

__device__ float d_S[2*NN*NN];   // Chebyshev supports S1, S2 (S0 = I implicit)

// ---------------------------------------------------------------------------
// packed f32x2 helpers
// ---------------------------------------------------------------------------
__device__ __forceinline__ u64 pk2(float a, float b) {
    u64 r; asm("mov.b64 %0,{%1,%2};" : "=l"(r) : "f"(a), "f"(b)); return r;
}
__device__ __forceinline__ u64 ffma2(u64 a, u64 b, u64 c) {
    u64 d; asm("fma.rn.f32x2 %0,%1,%2,%3;" : "=l"(d) : "l"(a), "l"(b), "l"(c)); return d;
}
__device__ __forceinline__ u64 fmul2(u64 a, u64 b) {
    u64 d; asm("mul.rn.f32x2 %0,%1,%2;" : "=l"(d) : "l"(a), "l"(b)); return d;
}
__device__ __forceinline__ void unpk(u64 v, float& a, float& b) {
    asm("mov.b64 {%0,%1},%2;" : "=f"(a), "=f"(b) : "l"(v));
}
__device__ __forceinline__ uint32_t smem_u32(const void* p) {
    uint32_t a;
    asm("{ .reg .u64 t; cvta.to.shared.u64 t, %1; cvt.u32.u64 %0, t; }"
        : "=r"(a) : "l"(p));
    return a;
}
__device__ __forceinline__ void cp_async16(uint32_t dst, const void* src) {
    asm volatile("cp.async.ca.shared.global [%0], [%1], 16;"
                 :: "r"(dst), "l"(src) : "memory");
}
#define CP_COMMIT() asm volatile("cp.async.commit_group;" ::: "memory")
#define CP_WAIT2()  asm volatile("cp.async.wait_group 2;" ::: "memory")

// ---------------------------------------------------------------------------
// warp-mma building blocks (fp16 single-pass)
// ---------------------------------------------------------------------------
#define LDSM4T(R, ADDR) \
    asm volatile("ldmatrix.sync.aligned.m8n8.x4.trans.shared.b16 {%0,%1,%2,%3}, [%4];" \
        : "=r"((R)[0]), "=r"((R)[1]), "=r"((R)[2]), "=r"((R)[3]) : "r"(ADDR))

#define MMA16816(D, A, B0, B1) \
    asm volatile("mma.sync.aligned.m16n8k16.row.col.f32.f16.f16.f32 " \
        "{%0,%1,%2,%3}, {%4,%5,%6,%7}, {%8,%9}, {%0,%1,%2,%3};" \
        : "+f"((D)[0]), "+f"((D)[1]), "+f"((D)[2]), "+f"((D)[3]) \
        : "r"((A)[0]), "r"((A)[1]), "r"((A)[2]), "r"((A)[3]), "r"(B0), "r"(B1))

// SMEM geometry (bytes)
#define A_STRIDE 208      // 96 fp16 = 192 B + 16 pad (rows hit all 32 banks)
#define B_STRIDE 144      // 64 fp16 = 128 B + 16 pad
#define A_BYTES  (KF*A_STRIDE)               // 39936
#define OFF_B    A_BYTES                     // 39936
#define RING_OFF (A_BYTES + KF*B_STRIDE)     // 67584: x ring, 4 slots x 2048 B
#define DSMEM_TOTAL (RING_OFF + 4*2048)      // 75776

// ---------------------------------------------------------------------------
// K0: supports = softmax(relu(E E^T), axis=1); S1, S2 = 2*S1@S1 - I
// ---------------------------------------------------------------------------
__global__ void k_supports(const float* __restrict__ E) {
    __shared__ float Es[NN*NN];
    __shared__ float P[NN*NN];
    __shared__ float sup[NN*NN];
    int t = threadIdx.x;
    if (t < NN*NN) Es[t] = E[t];
    __syncthreads();
    if (t < NN*NN) {
        int i = t / NN, j = t % NN;
        float s = 0.f;
        #pragma unroll
        for (int l = 0; l < NN; l++) s += Es[i*NN + l] * Es[j*NN + l];
        P[t] = fmaxf(s, 0.f);
    }
    __syncthreads();
    if (t < NN) {
        float mx = -1e30f;
        #pragma unroll
        for (int j = 0; j < NN; j++) mx = fmaxf(mx, P[t*NN + j]);
        float den = 0.f;
        #pragma unroll
        for (int j = 0; j < NN; j++) { float e = expf(P[t*NN + j] - mx); sup[t*NN + j] = e; den += e; }
        float inv = 1.f / den;
        #pragma unroll
        for (int j = 0; j < NN; j++) sup[t*NN + j] *= inv;
    }
    __syncthreads();
    if (t < NN*NN) {
        int i = t / NN, j = t % NN;
        float eye = (i == j) ? 1.f : 0.f;
        d_S[t] = sup[t];                       // S1
        float s = 0.f;
        #pragma unroll
        for (int l = 0; l < NN; l++) s += sup[i*NN + l] * sup[l*NN + j];
        d_S[NN*NN + t] = 2.f * s - eye;        // S2
    }
}

// ---------------------------------------------------------------------------
// Fused main kernel. One CTA per (b, 4-wide t-tile). 384 threads, occ 2.
// Phase 1: n-contraction (cp.async x ring), fp32 accum, cvt fp16,
//          store A[kf][mt] K-major (mt = m*4 + t, padded to 96).
// Phase 2: 12 warps = (mt-tile 0..5, n-half); fp16 mma single-pass; relu.
// ---------------------------------------------------------------------------
__global__ void __launch_bounds__(384, 2) k_main(
    const float* __restrict__ x,
    const float* __restrict__ att,
    const float* __restrict__ theta_g,
    float* __restrict__ out)
{
    extern __shared__ char dsm[];
    __shared__ u64 a2d[2*NN*NN];
    __shared__ u64 diag[NN];

    const int tid = threadIdx.x;
    const int b   = blockIdx.y;
    const int tt0 = blockIdx.x * TT;
    const uint32_t sbase = smem_u32(dsm);
    const uint32_t ringb = sbase + RING_OFF;
    const float*   xb    = x + (size_t)b*NN*NF*NT + tt0;
    const float*   ringf = (const float*)(dsm + RING_OFF);

    // cp.async: chunk c = n rows {2c,2c+1}, 2048 B, 128 issuer threads,
    // one 16B line (= 4 t) per (n,f) per issuer.
    const int cn2 = tid >> 6;          // 0..1 (valid tid<128)
    const int cf  = tid & 63;
    const float*   csrc0 = xb + ((size_t)cn2*NF + cf)*NT;
    const uint32_t cdst0 = ringb + (uint32_t)((cn2 << 10) | (cf << 4));

    // ---- prologue: prefetch chunks 0..2 ----
    if (tid < 128) {
        cp_async16(cdst0,        csrc0);               CP_COMMIT();
        cp_async16(cdst0 + 2048, csrc0 + 2*NF*NT);     CP_COMMIT();
        cp_async16(cdst0 + 4096, csrc0 + 4*NF*NT);     CP_COMMIT();
    }

    // ---- stage theta fp16 into B[kf][o] (stride 144 B) ----
    for (int i = tid; i < KF*NO/2; i += 384) {          // o-pairs
        int kf = i >> 5;
        int op = (i & 31) * 2;
        float2 v = *(const float2*)(theta_g + kf*NO + op);
        __half2 h = __floats2half2_rn(v.x, v.y);
        *(uint32_t*)(dsm + OFF_B + kf*B_STRIDE + op*2) = *(uint32_t*)&h;
    }
    // ---- stage a2d (dup u64) + diag ----
    for (int idx = tid; idx < 2*NN*NN + NN; idx += 384) {
        if (idx < 2*NN*NN) {
            int kk = idx / (NN*NN);
            int r  = idx % (NN*NN);
            int m = r / NN, n = r % NN;
            float v = d_S[kk*NN*NN + n*NN + m] * att[(b*NN + n)*NN + m];
            a2d[idx] = pk2(v, v);
        } else {
            int m = idx - 2*NN*NN;
            diag[m] = pk2(att[(b*NN + m)*NN + m], att[(b*NN + m)*NN + m]);
        }
    }
    __syncthreads();

    // ---- phase 1: thread = (k, f, t-pair); 3*64*2 = 384 items ----
    {
        const int k  = tid >> 7;            // warp-uniform
        const int f  = (tid >> 1) & 63;
        const int tp = tid & 1;
        const u64* ap = a2d + (k >= 1 ? (k-1)*NN*NN : 0);

        u64 acc[NN];
        #pragma unroll
        for (int m = 0; m < NN; m++) acc[m] = 0ULL;

        #pragma unroll
        for (int c = 0; c < NN/2; c++) {
            if (tid < 128) CP_WAIT2();
            __syncthreads();
            if (tid < 128) {
                if (c + 3 < NN/2)
                    cp_async16(cdst0 + (((c+3) & 3) << 11),
                               csrc0 + (size_t)(2*(c+3))*NF*NT);
                CP_COMMIT();
            }
            const float* xp = ringf + ((c & 3) << 9);
            u64 xv0 = *(const u64*)(xp + f*4 + tp*2);
            u64 xv1 = *(const u64*)(xp + 256 + f*4 + tp*2);
            if (k == 0) {
                acc[2*c]   = fmul2(diag[2*c],   xv0);
                acc[2*c+1] = fmul2(diag[2*c+1], xv1);
            } else {
                #pragma unroll
                for (int m = 0; m < NN; m++) {
                    ulonglong2 aa = *(const ulonglong2*)(ap + m*NN + 2*c);
                    acc[m] = ffma2(aa.x, xv0, acc[m]);
                    acc[m] = ffma2(aa.y, xv1, acc[m]);
                }
            }
        }

        // cvt fp16 + store A[kf=k*64+f][mt = m*4 + tp*2 + {0,1}]
        char* arow = dsm + (k*64 + f)*A_STRIDE + tp*4;
        #pragma unroll
        for (int m = 0; m < NN; m++) {
            float v0, v1; unpk(acc[m], v0, v1);
            __half2 h = __floats2half2_rn(v0, v1);
            *(uint32_t*)(arow + m*8) = *(uint32_t*)&h;
        }
    }
    __syncthreads();

    // ---- phase 2: 12 warps = (mt-tile 0..5, n-half); fp16 single-pass ----
    {
        const int w    = tid >> 5;
        const int lane = tid & 31;
        const int mt  = w >> 1;             // 0..5
        const int nh  = w & 1;              // 0..1
        const int m0b = mt * 16;            // A col base (mt rows)
        const int n0  = nh * 32;

        // ldmatrix.x4.trans lane address components (R10-verified mapping)
        const int lrow = (lane & 7) + ((lane >> 4) << 3);   // kf-row in k16
        const int lga  = ((lane >> 3) & 1) * 8;             // 8-col group
        uint32_t aA  = sbase + lrow*A_STRIDE + (m0b + lga)*2;
        uint32_t aB0 = sbase + OFF_B + lrow*B_STRIDE + (n0 + lga)*2;
        uint32_t aB1 = aB0 + 32;                            // n0+16 block

        float acc[16];
        #pragma unroll
        for (int i = 0; i < 16; i++) acc[i] = 0.f;

        #pragma unroll 4
        for (int s = 0; s < 12; s++) {
            uint32_t ah[4], bh0[4], bh1[4];
            LDSM4T(ah,  aA  + s*(16*A_STRIDE));
            LDSM4T(bh0, aB0 + s*(16*B_STRIDE));
            LDSM4T(bh1, aB1 + s*(16*B_STRIDE));
            MMA16816(acc +  0, ah, bh0[0], bh0[2]);
            MMA16816(acc +  4, ah, bh0[1], bh0[3]);
            MMA16816(acc +  8, ah, bh1[0], bh1[2]);
            MMA16816(acc + 12, ah, bh1[1], bh1[3]);
        }

        // ---- epilogue: D(row=mt-row, col=o) -> relu -> out[b][m][o][t] ----
        // frag row r = lane/4 + 8i -> m = 4*mt + (lane>>4) + 2i, t = (lane>>2)&3
        const int tq   = (lane >> 2) & 3;
        const int mrow = lane >> 4;
        const int q2   = (lane & 3) * 2;
        #pragma unroll
        for (int j = 0; j < 4; j++) {
            #pragma unroll
            for (int i = 0; i < 2; i++) {
                int m = 4*mt + mrow + 2*i;
                if (m < NN) {
                    int o = n0 + j*8 + q2;
                    float* op = out + ((size_t)(b*NN + m)*NO + o)*NT + tt0 + tq;
                    op[0]  = fmaxf(acc[j*4 + i*2 + 0], 0.f);
                    op[NT] = fmaxf(acc[j*4 + i*2 + 1], 0.f);
                }
            }
        }
    }
}

// ---------------------------------------------------------------------------
extern "C" void kernel_launch(void* const* d_in, const int* in_sizes, int n_in,
                              void* d_out, int out_size)
{
    const float* x     = (const float*)d_in[0];   // [B,N,F_in,T]
    const float* att   = (const float*)d_in[1];   // [B,N,N]
    const float* theta = (const float*)d_in[2];   // [K,F_in,F_out]
    const float* emb   = (const float*)d_in[3];   // [N,N]
    float* out = (float*)d_out;                   // [B,N,F_out,T]

    k_supports<<<1, 512>>>(emb);

    cudaFuncSetAttribute(k_main, cudaFuncAttributeMaxDynamicSharedMemorySize,
                         DSMEM_TOTAL);
    dim3 grid(NT/TT, NB);
    k_main<<<grid, 384, DSMEM_TOTAL>>>(x, att, theta, out);
}

// round 13
// speedup vs baseline: 2.1538x; 1.4111x over previous
#include <cuda_runtime.h>
#include <cuda_fp16.h>
#include <cstdint>

#define NB 64
#define NN 22
#define NF 64
#define NO 64
#define NT 512
#define TT 4              // t-tile width per CTA
#define KF 192            // combined (k,f) contraction dim

typedef unsigned long long u64;

__device__ float d_S[2*NN*NN];     // Chebyshev supports S1, S2 (S0 = I implicit)
__device__ __half d_thT[NO*KF];    // theta^T fp16 [o][kf]

// ---------------------------------------------------------------------------
__device__ __forceinline__ uint32_t smem_u32(const void* p) {
    uint32_t a;
    asm("{ .reg .u64 t; cvta.to.shared.u64 t, %1; cvt.u32.u64 %0, t; }"
        : "=r"(a) : "l"(p));
    return a;
}
__device__ __forceinline__ void cp_async16(uint32_t dst, const void* src) {
    asm volatile("cp.async.ca.shared.global [%0], [%1], 16;"
                 :: "r"(dst), "l"(src) : "memory");
}
#define CP_COMMIT() asm volatile("cp.async.commit_group;" ::: "memory")
#define CP_WAIT2()  asm volatile("cp.async.wait_group 2;" ::: "memory")

// ---------------------------------------------------------------------------
// warp-mma building blocks
// ---------------------------------------------------------------------------
#define LDSM4T(R, ADDR) \
    asm volatile("ldmatrix.sync.aligned.m8n8.x4.trans.shared.b16 {%0,%1,%2,%3}, [%4];" \
        : "=r"((R)[0]), "=r"((R)[1]), "=r"((R)[2]), "=r"((R)[3]) : "r"(ADDR))

#define LDSM4(R, ADDR) \
    asm volatile("ldmatrix.sync.aligned.m8n8.x4.shared.b16 {%0,%1,%2,%3}, [%4];" \
        : "=r"((R)[0]), "=r"((R)[1]), "=r"((R)[2]), "=r"((R)[3]) : "r"(ADDR))

#define MMA16816(D, A, B0, B1) \
    asm volatile("mma.sync.aligned.m16n8k16.row.col.f32.f16.f16.f32 " \
        "{%0,%1,%2,%3}, {%4,%5,%6,%7}, {%8,%9}, {%0,%1,%2,%3};" \
        : "+f"((D)[0]), "+f"((D)[1]), "+f"((D)[2]), "+f"((D)[3]) \
        : "r"((A)[0]), "r"((A)[1]), "r"((A)[2]), "r"((A)[3]), "r"(B0), "r"(B1))

// SMEM geometry (bytes)
#define A_STRIDE 208      // A[kf][mt]: 96 fp16 = 192 B + 16 pad
#define B_STRIDE 400      // B[o][kf]:  192 fp16 = 384 B + 16 pad
#define A_BYTES  (KF*A_STRIDE)               // 39936
#define OFF_B    A_BYTES                     // 39936
#define RING_OFF (A_BYTES + NO*B_STRIDE)     // 65536: x ring, 4 slots x 2048 B
#define DSMEM_TOTAL (RING_OFF + 4*2048)      // 73728

// ---------------------------------------------------------------------------
// K_prep: supports = softmax(relu(E E^T), axis=1); S1, S2 = 2*S1@S1 - I;
//         plus theta^T fp16 [o][kf] for cp.async staging in k_main.
// ---------------------------------------------------------------------------
__global__ void k_prep(const float* __restrict__ E, const float* __restrict__ theta) {
    __shared__ float Es[NN*NN];
    __shared__ float P[NN*NN];
    __shared__ float sup[NN*NN];
    int t = threadIdx.x;
    for (int i = t; i < NO*KF; i += 512) {
        int o = i / KF, kf = i % KF;
        d_thT[i] = __float2half(theta[kf*NO + o]);
    }
    if (t < NN*NN) Es[t] = E[t];
    __syncthreads();
    if (t < NN*NN) {
        int i = t / NN, j = t % NN;
        float s = 0.f;
        #pragma unroll
        for (int l = 0; l < NN; l++) s += Es[i*NN + l] * Es[j*NN + l];
        P[t] = fmaxf(s, 0.f);
    }
    __syncthreads();
    if (t < NN) {
        float mx = -1e30f;
        #pragma unroll
        for (int j = 0; j < NN; j++) mx = fmaxf(mx, P[t*NN + j]);
        float den = 0.f;
        #pragma unroll
        for (int j = 0; j < NN; j++) { float e = expf(P[t*NN + j] - mx); sup[t*NN + j] = e; den += e; }
        float inv = 1.f / den;
        #pragma unroll
        for (int j = 0; j < NN; j++) sup[t*NN + j] *= inv;
    }
    __syncthreads();
    if (t < NN*NN) {
        int i = t / NN, j = t % NN;
        float eye = (i == j) ? 1.f : 0.f;
        d_S[t] = sup[t];                       // S1
        float s = 0.f;
        #pragma unroll
        for (int l = 0; l < NN; l++) s += sup[i*NN + l] * sup[l*NN + j];
        d_S[NN*NN + t] = 2.f * s - eye;        // S2
    }
}

// ---------------------------------------------------------------------------
// Fused main kernel. One CTA per (b, 4-wide t-tile). 384 threads, occ 2.
// Phase 1: n-contraction (cp.async x ring, scalar FFMA with raw-float2 a2),
//          cvt fp16, store A[kf][mt] K-major.
// Phase 2: 12 warps = (mt-tile, n-half); A trans-LDSM, B non-trans LDSM.
// ---------------------------------------------------------------------------
__global__ void __launch_bounds__(384, 2) k_main(
    const float* __restrict__ x,
    const float* __restrict__ att,
    float* __restrict__ out)
{
    extern __shared__ char dsm[];
    __shared__ float2 a2f[2*NN*11];    // raw (non-dup) coeff pairs over n
    __shared__ float  diag[NN];

    const int tid = threadIdx.x;
    const int b   = blockIdx.y;
    const int tt0 = blockIdx.x * TT;
    const uint32_t sbase = smem_u32(dsm);
    const uint32_t ringb = sbase + RING_OFF;
    const float*   xb    = x + (size_t)b*NN*NF*NT + tt0;
    const float*   ringf = (const float*)(dsm + RING_OFF);

    // cp.async: x chunk c = n rows {2c,2c+1}, 2048 B, 128 issuer threads.
    const int cn2 = tid >> 6;          // 0..1 (valid tid<128)
    const int cf  = tid & 63;
    const float*   csrc0 = xb + ((size_t)cn2*NF + cf)*NT;
    const uint32_t cdst0 = ringb + (uint32_t)((cn2 << 10) | (cf << 4));

    // ---- prologue: B(theta^T) staging + x chunks 0..2; all async ops by
    //      tid<128 so group accounting is single-domain. G0 = {B, c0}. ----
    if (tid < 128) {
        #pragma unroll
        for (int j = 0; j < 12; j++) {
            int i = tid + j*128;                  // 0..1535
            int o = i / 24, ch = i % 24;
            cp_async16(sbase + OFF_B + o*B_STRIDE + ch*16, d_thT + o*KF + ch*8);
        }
        cp_async16(cdst0,        csrc0);               CP_COMMIT();
        cp_async16(cdst0 + 2048, csrc0 + 2*NF*NT);     CP_COMMIT();
        cp_async16(cdst0 + 4096, csrc0 + 4*NF*NT);     CP_COMMIT();
    }

    // ---- stage a2f (raw float2 over n-pairs) + diag ----
    for (int idx = tid; idx < 2*NN*11 + NN; idx += 384) {
        if (idx < 2*NN*11) {
            int kk = idx / (NN*11);
            int r  = idx % (NN*11);
            int m = r / 11, c = r % 11;
            float v0 = d_S[kk*NN*NN + (2*c+0)*NN + m] * att[(b*NN + 2*c+0)*NN + m];
            float v1 = d_S[kk*NN*NN + (2*c+1)*NN + m] * att[(b*NN + 2*c+1)*NN + m];
            a2f[idx] = make_float2(v0, v1);
        } else {
            int m = idx - 2*NN*11;
            diag[m] = att[(b*NN + m)*NN + m];
        }
    }
    __syncthreads();

    // ---- phase 1: thread = (k, f, t-pair); 3*64*2 = 384 items ----
    {
        const int k  = tid >> 7;            // warp-uniform
        const int f  = (tid >> 1) & 63;
        const int tp = tid & 1;
        const float2* ap = a2f + (k >= 1 ? (k-1)*NN*11 : 0);

        float a0[NN], a1[NN];
        #pragma unroll
        for (int m = 0; m < NN; m++) { a0[m] = 0.f; a1[m] = 0.f; }

        #pragma unroll
        for (int c = 0; c < NN/2; c++) {
            if (tid < 128) CP_WAIT2();
            __syncthreads();
            if (tid < 128) {
                if (c + 3 < NN/2)
                    cp_async16(cdst0 + (((c+3) & 3) << 11),
                               csrc0 + (size_t)(2*(c+3))*NF*NT);
                CP_COMMIT();
            }
            const float* xp = ringf + ((c & 3) << 9);
            float2 xv0 = *(const float2*)(xp + f*4 + tp*2);        // n = 2c
            float2 xv1 = *(const float2*)(xp + 256 + f*4 + tp*2);  // n = 2c+1
            if (k == 0) {
                a0[2*c]   = diag[2*c]   * xv0.x;  a1[2*c]   = diag[2*c]   * xv0.y;
                a0[2*c+1] = diag[2*c+1] * xv1.x;  a1[2*c+1] = diag[2*c+1] * xv1.y;
            } else {
                #pragma unroll
                for (int m = 0; m < NN; m++) {
                    float2 aa = ap[m*11 + c];          // LDS.64 broadcast
                    a0[m] = fmaf(aa.x, xv0.x, a0[m]);
                    a0[m] = fmaf(aa.y, xv1.x, a0[m]);
                    a1[m] = fmaf(aa.x, xv0.y, a1[m]);
                    a1[m] = fmaf(aa.y, xv1.y, a1[m]);
                }
            }
        }

        // cvt fp16 + store A[kf=k*64+f][mt = m*4 + tp*2 + {0,1}]
        char* arow = dsm + (k*64 + f)*A_STRIDE + tp*4;
        #pragma unroll
        for (int m = 0; m < NN; m++) {
            __half2 h = __floats2half2_rn(a0[m], a1[m]);
            *(uint32_t*)(arow + m*8) = *(uint32_t*)&h;
        }
    }
    __syncthreads();

    // ---- phase 2: 12 warps = (mt-tile 0..5, n-half); A trans, B non-trans ----
    {
        const int w    = tid >> 5;
        const int lane = tid & 31;
        const int mt  = w >> 1;             // 0..5
        const int nh  = w & 1;              // 0..1
        const int m0b = mt * 16;            // A col base (mt rows)
        const int n0  = nh * 32;

        // A (trans, R10/R12-verified): rows = kf, cols = mt
        const int lrow = (lane & 7) + ((lane >> 4) << 3);
        const int lga  = ((lane >> 3) & 1) * 8;
        uint32_t aA = sbase + lrow*A_STRIDE + (m0b + lga)*2;

        // B (non-trans): rows = o, cols = kf.
        // x4 matrices: {o0-7,kf0-7},{o0-7,kf8-15},{o8-15,kf0-7},{o8-15,kf8-15}
        const int borow = ((lane >> 4) << 3) + (lane & 7);
        uint32_t aB0 = sbase + OFF_B + (n0 + borow)*B_STRIDE + ((lane >> 3) & 1)*16;
        uint32_t aB1 = aB0 + 16*B_STRIDE;   // o rows n0+16..n0+31

        float acc[16];
        #pragma unroll
        for (int i = 0; i < 16; i++) acc[i] = 0.f;

        #pragma unroll 4
        for (int s = 0; s < 12; s++) {
            uint32_t ah[4], b0[4], b1[4];
            LDSM4T(ah, aA  + s*(16*A_STRIDE));
            LDSM4 (b0, aB0 + s*32);
            LDSM4 (b1, aB1 + s*32);
            MMA16816(acc +  0, ah, b0[0], b0[1]);   // o n0+0..7
            MMA16816(acc +  4, ah, b0[2], b0[3]);   // o n0+8..15
            MMA16816(acc +  8, ah, b1[0], b1[1]);   // o n0+16..23
            MMA16816(acc + 12, ah, b1[2], b1[3]);   // o n0+24..31
        }

        // ---- epilogue: D(row=mt-row, col=o) -> relu -> out[b][m][o][t] ----
        const int tq   = (lane >> 2) & 3;
        const int mrow = lane >> 4;
        const int q2   = (lane & 3) * 2;
        #pragma unroll
        for (int j = 0; j < 4; j++) {
            #pragma unroll
            for (int i = 0; i < 2; i++) {
                int m = 4*mt + mrow + 2*i;
                if (m < NN) {
                    int o = n0 + j*8 + q2;
                    float* op = out + ((size_t)(b*NN + m)*NO + o)*NT + tt0 + tq;
                    op[0]  = fmaxf(acc[j*4 + i*2 + 0], 0.f);
                    op[NT] = fmaxf(acc[j*4 + i*2 + 1], 0.f);
                }
            }
        }
    }
}

// ---------------------------------------------------------------------------
extern "C" void kernel_launch(void* const* d_in, const int* in_sizes, int n_in,
                              void* d_out, int out_size)
{
    const float* x     = (const float*)d_in[0];   // [B,N,F_in,T]
    const float* att   = (const float*)d_in[1];   // [B,N,N]
    const float* theta = (const float*)d_in[2];   // [K,F_in,F_out]
    const float* emb   = (const float*)d_in[3];   // [N,N]
    float* out = (float*)d_out;                   // [B,N,F_out,T]

    k_prep<<<1, 512>>>(emb, theta);

    cudaFuncSetAttribute(k_main, cudaFuncAttributeMaxDynamicSharedMemorySize,
                         DSMEM_TOTAL);
    dim3 grid(NT/TT, NB);
    k_main<<<grid, 384, DSMEM_TOTAL>>>(x, att, out);
}